// round 1
// baseline (speedup 1.0000x reference)
#include <cuda_runtime.h>
#include <math.h>

// Problem constants
#define NTOK   8192      // B*T
#define DDIM   1024
#define FDIM   2816
#define NEXP   8
#define CAP    8192      // worst-case tokens per expert

// ---------------- device scratch (no cudaMalloc allowed) ----------------
__device__ int   g_count[NEXP];
__device__ int   g_tok[NEXP * CAP];          // token id per (expert, pos)
__device__ int   g_slot[NTOK * 2];           // slot = e*CAP + pos for each (token,k)
__device__ float g_wt[NTOK * 2];             // combine weight for each (token,k)
__device__ float g_act[(size_t)NEXP * CAP * FDIM];   // silu(gate)*up, fp32
__device__ float g_y[(size_t)NEXP * CAP * DDIM];     // down output per slot

// ---------------- kernel 0: reset expert counters ----------------
__global__ void reset_kernel() {
    if (threadIdx.x < NEXP) g_count[threadIdx.x] = 0;
}

// ---------------- kernel 1: router (warp per token) ----------------
__global__ void router_kernel(const float* __restrict__ X,
                              const float* __restrict__ RW) {
    __shared__ float sW[NEXP * DDIM];   // transposed: sW[e*DDIM + d]
    const int tid = threadIdx.x;        // 128 threads
    for (int i = tid; i < NEXP * DDIM; i += 128) {
        int d = i >> 3, e = i & 7;      // RW is [D, E] row-major
        sW[e * DDIM + d] = RW[i];
    }
    __syncthreads();

    const int warp = tid >> 5, lane = tid & 31;
    const int t = blockIdx.x * 4 + warp;
    const float* xr = X + (size_t)t * DDIM;

    float acc[NEXP];
#pragma unroll
    for (int e = 0; e < NEXP; e++) acc[e] = 0.f;

    for (int d = lane; d < DDIM; d += 32) {
        float xv = xr[d];
#pragma unroll
        for (int e = 0; e < NEXP; e++) acc[e] += xv * sW[e * DDIM + d];
    }
#pragma unroll
    for (int e = 0; e < NEXP; e++) {
#pragma unroll
        for (int off = 16; off > 0; off >>= 1)
            acc[e] += __shfl_xor_sync(0xFFFFFFFFu, acc[e], off);
    }

    if (lane == 0) {
        // top-2 over scores (softmax is monotone; ties -> lowest index, like jax top_k)
        int i0 = 0; float s0 = acc[0];
#pragma unroll
        for (int e = 1; e < NEXP; e++) if (acc[e] > s0) { s0 = acc[e]; i0 = e; }
        int i1 = -1; float s1 = -INFINITY;
#pragma unroll
        for (int e = 0; e < NEXP; e++) if (e != i0 && acc[e] > s1) { s1 = acc[e]; i1 = e; }

        // normalized top-2 softmax weights: w0 = e^{s0}/(e^{s0}+e^{s1})
        float w0 = 1.f / (1.f + expf(s1 - s0));
        float w1 = 1.f - w0;

        int p0 = atomicAdd(&g_count[i0], 1);
        int p1 = atomicAdd(&g_count[i1], 1);
        g_tok[i0 * CAP + p0] = t;
        g_tok[i1 * CAP + p1] = t;
        g_slot[2 * t + 0] = i0 * CAP + p0;  g_wt[2 * t + 0] = w0;
        g_slot[2 * t + 1] = i1 * CAP + p1;  g_wt[2 * t + 1] = w1;
    }
}

// ---------------- kernel 2: fused gate+up GEMM + SiLU epilogue ----------------
// C tiles: 64 (tokens) x 64 (F), K-tiles of 16 over D. 256 threads, 4x4 micro-tile
// for BOTH gate and up (shared A tile).
__global__ void __launch_bounds__(256)
gateup_kernel(const float* __restrict__ X,
              const float* __restrict__ Wg,
              const float* __restrict__ Wu) {
    const int e = blockIdx.z;
    const int cnt = g_count[e];
    const int m0 = blockIdx.x * 64;
    if (m0 >= cnt) return;
    const int n0 = blockIdx.y * 64;

    __shared__ float As[16 * 64];   // [k][row]
    __shared__ float Bg[16 * 64];   // [k][col]
    __shared__ float Bu[16 * 64];

    const int tid = threadIdx.x;
    // A-load mapping: 64 rows x 16 k, float4 along k
    const int arow = tid >> 2;
    const int ak   = (tid & 3) * 4;
    const bool aval = (m0 + arow) < cnt;
    const int tok = aval ? g_tok[e * CAP + m0 + arow] : 0;
    const float* xrow = X + (size_t)tok * DDIM + ak;
    // B-load mapping: 16 k-rows x 64 cols, float4 along cols
    const int bk = tid >> 4;          // 0..15
    const int bn = (tid & 15) * 4;    // 0..60
    const float* wgp = Wg + ((size_t)e * DDIM + bk) * FDIM + n0 + bn;
    const float* wup = Wu + ((size_t)e * DDIM + bk) * FDIM + n0 + bn;

    const int tx = tid & 15, ty = tid >> 4;

    float accg[4][4], accu[4][4];
#pragma unroll
    for (int i = 0; i < 4; i++)
#pragma unroll
        for (int j = 0; j < 4; j++) { accg[i][j] = 0.f; accu[i][j] = 0.f; }

    for (int k0 = 0; k0 < DDIM; k0 += 16) {
        float4 av = aval ? *(const float4*)(xrow + k0) : make_float4(0.f, 0.f, 0.f, 0.f);
        As[(ak + 0) * 64 + arow] = av.x;
        As[(ak + 1) * 64 + arow] = av.y;
        As[(ak + 2) * 64 + arow] = av.z;
        As[(ak + 3) * 64 + arow] = av.w;
        *(float4*)&Bg[bk * 64 + bn] = *(const float4*)(wgp + (size_t)k0 * FDIM);
        *(float4*)&Bu[bk * 64 + bn] = *(const float4*)(wup + (size_t)k0 * FDIM);
        __syncthreads();
#pragma unroll
        for (int kk = 0; kk < 16; kk++) {
            float4 a  = *(const float4*)&As[kk * 64 + ty * 4];
            float4 bg = *(const float4*)&Bg[kk * 64 + tx * 4];
            float4 bu = *(const float4*)&Bu[kk * 64 + tx * 4];
            float aa[4]  = {a.x, a.y, a.z, a.w};
            float bgj[4] = {bg.x, bg.y, bg.z, bg.w};
            float buj[4] = {bu.x, bu.y, bu.z, bu.w};
#pragma unroll
            for (int i = 0; i < 4; i++)
#pragma unroll
                for (int j = 0; j < 4; j++) {
                    accg[i][j] += aa[i] * bgj[j];
                    accu[i][j] += aa[i] * buj[j];
                }
        }
        __syncthreads();
    }

    // epilogue: act = silu(gate) * up
    const size_t base = ((size_t)e * CAP + m0) * FDIM;
#pragma unroll
    for (int i = 0; i < 4; i++) {
        int r = ty * 4 + i;
        if (m0 + r < cnt) {
#pragma unroll
            for (int j = 0; j < 4; j++) {
                float g = accg[i][j], u = accu[i][j];
                float s = g / (1.f + expf(-g));
                g_act[base + (size_t)r * FDIM + n0 + tx * 4 + j] = s * u;
            }
        }
    }
}

// ---------------- kernel 3: down-proj GEMM ----------------
__global__ void __launch_bounds__(256)
down_kernel(const float* __restrict__ Wd) {
    const int e = blockIdx.z;
    const int cnt = g_count[e];
    const int m0 = blockIdx.x * 64;
    if (m0 >= cnt) return;
    const int n0 = blockIdx.y * 64;   // over D

    __shared__ float As[16 * 64];
    __shared__ float Bs[16 * 64];

    const int tid = threadIdx.x;
    const int arow = tid >> 2;
    const int ak   = (tid & 3) * 4;
    const bool aval = (m0 + arow) < cnt;
    const float* arp = g_act + ((size_t)e * CAP + m0 + arow) * FDIM + ak;
    const int bk = tid >> 4;
    const int bn = (tid & 15) * 4;
    const float* wdp = Wd + ((size_t)e * FDIM + bk) * DDIM + n0 + bn;

    const int tx = tid & 15, ty = tid >> 4;
    float acc[4][4];
#pragma unroll
    for (int i = 0; i < 4; i++)
#pragma unroll
        for (int j = 0; j < 4; j++) acc[i][j] = 0.f;

    for (int k0 = 0; k0 < FDIM; k0 += 16) {
        float4 av = aval ? *(const float4*)(arp + k0) : make_float4(0.f, 0.f, 0.f, 0.f);
        As[(ak + 0) * 64 + arow] = av.x;
        As[(ak + 1) * 64 + arow] = av.y;
        As[(ak + 2) * 64 + arow] = av.z;
        As[(ak + 3) * 64 + arow] = av.w;
        *(float4*)&Bs[bk * 64 + bn] = *(const float4*)(wdp + (size_t)k0 * DDIM);
        __syncthreads();
#pragma unroll
        for (int kk = 0; kk < 16; kk++) {
            float4 a = *(const float4*)&As[kk * 64 + ty * 4];
            float4 b = *(const float4*)&Bs[kk * 64 + tx * 4];
            float aa[4] = {a.x, a.y, a.z, a.w};
            float bb[4] = {b.x, b.y, b.z, b.w};
#pragma unroll
            for (int i = 0; i < 4; i++)
#pragma unroll
                for (int j = 0; j < 4; j++) acc[i][j] += aa[i] * bb[j];
        }
        __syncthreads();
    }

    const size_t base = ((size_t)e * CAP + m0) * DDIM;
#pragma unroll
    for (int i = 0; i < 4; i++) {
        int r = ty * 4 + i;
        if (m0 + r < cnt) {
#pragma unroll
            for (int j = 0; j < 4; j++)
                g_y[base + (size_t)r * DDIM + n0 + tx * 4 + j] = acc[i][j];
        }
    }
}

// ---------------- kernel 4: weighted combine ----------------
__global__ void combine_kernel(float* __restrict__ out) {
    const int g = blockIdx.x * blockDim.x + threadIdx.x;   // over NTOK*256 float4s
    const int t = g >> 8;
    const int c = g & 255;
    const int s0 = g_slot[2 * t], s1 = g_slot[2 * t + 1];
    const float w0 = g_wt[2 * t], w1 = g_wt[2 * t + 1];
    const float4* Y = (const float4*)g_y;
    float4 a = Y[(size_t)s0 * 256 + c];
    float4 b = Y[(size_t)s1 * 256 + c];
    float4 o;
    o.x = w0 * a.x + w1 * b.x;
    o.y = w0 * a.y + w1 * b.y;
    o.z = w0 * a.z + w1 * b.z;
    o.w = w0 * a.w + w1 * b.w;
    ((float4*)out)[g] = o;
}

// ---------------- launch ----------------
extern "C" void kernel_launch(void* const* d_in, const int* in_sizes, int n_in,
                              void* d_out, int out_size) {
    const float* x  = (const float*)d_in[0];   // (B,T,D)
    const float* rw = (const float*)d_in[1];   // (D,E)
    const float* wg = (const float*)d_in[2];   // (E,D,F)
    const float* wu = (const float*)d_in[3];   // (E,D,F)
    const float* wd = (const float*)d_in[4];   // (E,F,D)
    float* out = (float*)d_out;

    reset_kernel<<<1, 32>>>();
    router_kernel<<<NTOK / 4, 128>>>(x, rw);

    dim3 g2(CAP / 64, FDIM / 64, NEXP);
    gateup_kernel<<<g2, 256>>>(x, wg, wu);

    dim3 g3(CAP / 64, DDIM / 64, NEXP);
    down_kernel<<<g3, 256>>>(wd);

    combine_kernel<<<(NTOK * 256) / 256, 256>>>(out);
}

// round 3
// speedup vs baseline: 3.4953x; 3.4953x over previous
#include <cuda_runtime.h>
#include <math.h>
#include <stdint.h>

#define NTOK 8192
#define DDIM 1024
#define FDIM 2816
#define NEXP 8
#define CAP  8192

// ---------------- device scratch ----------------
__device__ int   g_count[NEXP];
__device__ int   g_tok[NEXP * CAP];
__device__ int   g_slot[NTOK * 2];
__device__ float g_wt[NTOK * 2];
__device__ float g_act[(size_t)NEXP * CAP * FDIM];
__device__ float g_y[(size_t)NEXP * CAP * DDIM];

// ---------------- helpers ----------------
__device__ __forceinline__ uint32_t smem_u32(const void* p) {
    uint32_t a;
    asm("{ .reg .u64 t; cvta.to.shared.u64 t, %1; cvt.u32.u64 %0, t; }" : "=r"(a) : "l"(p));
    return a;
}
__device__ __forceinline__ uint32_t cvt_tf32(float x) {
    uint32_t r; asm("cvt.rna.tf32.f32 %0, %1;" : "=r"(r) : "f"(x)); return r;
}

#define CPA(dst, src, n) asm volatile("cp.async.cg.shared.global [%0], [%1], 16, %2;" :: "r"(dst), "l"(src), "r"(n) : "memory")
#define CPA_COMMIT()     asm volatile("cp.async.commit_group;" ::: "memory")
#define CPA_WAIT2()      asm volatile("cp.async.wait_group 2;" ::: "memory")

#define MMA_TF32(d, a, b) \
    asm volatile("mma.sync.aligned.m16n8k8.row.col.f32.tf32.tf32.f32 " \
        "{%0,%1,%2,%3}, {%4,%5,%6,%7}, {%8,%9}, {%0,%1,%2,%3};" \
        : "+f"((d)[0]), "+f"((d)[1]), "+f"((d)[2]), "+f"((d)[3]) \
        : "r"((a)[0]), "r"((a)[1]), "r"((a)[2]), "r"((a)[3]), "r"((b)[0]), "r"((b)[1]))

// ---------------- kernel 0: reset ----------------
__global__ void reset_kernel() {
    if (threadIdx.x < NEXP) g_count[threadIdx.x] = 0;
}

// ---------------- kernel 1: router ----------------
__global__ void router_kernel(const float* __restrict__ X, const float* __restrict__ RW) {
    __shared__ float sW[NEXP * DDIM];
    const int tid = threadIdx.x;
    for (int i = tid; i < NEXP * DDIM; i += 128) {
        int d = i >> 3, e = i & 7;
        sW[e * DDIM + d] = RW[i];
    }
    __syncthreads();
    const int warp = tid >> 5, lane = tid & 31;
    const int t = blockIdx.x * 4 + warp;
    const float* xr = X + (size_t)t * DDIM;
    float acc[NEXP];
#pragma unroll
    for (int e = 0; e < NEXP; e++) acc[e] = 0.f;
    for (int d = lane; d < DDIM; d += 32) {
        float xv = xr[d];
#pragma unroll
        for (int e = 0; e < NEXP; e++) acc[e] += xv * sW[e * DDIM + d];
    }
#pragma unroll
    for (int e = 0; e < NEXP; e++)
#pragma unroll
        for (int off = 16; off > 0; off >>= 1)
            acc[e] += __shfl_xor_sync(0xFFFFFFFFu, acc[e], off);
    if (lane == 0) {
        int i0 = 0; float s0 = acc[0];
#pragma unroll
        for (int e = 1; e < NEXP; e++) if (acc[e] > s0) { s0 = acc[e]; i0 = e; }
        int i1 = -1; float s1 = -INFINITY;
#pragma unroll
        for (int e = 0; e < NEXP; e++) if (e != i0 && acc[e] > s1) { s1 = acc[e]; i1 = e; }
        float w0 = 1.f / (1.f + expf(s1 - s0));
        float w1 = 1.f - w0;
        int p0 = atomicAdd(&g_count[i0], 1);
        int p1 = atomicAdd(&g_count[i1], 1);
        g_tok[i0 * CAP + p0] = t;
        g_tok[i1 * CAP + p1] = t;
        g_slot[2 * t + 0] = i0 * CAP + p0;  g_wt[2 * t + 0] = w0;
        g_slot[2 * t + 1] = i1 * CAP + p1;  g_wt[2 * t + 1] = w1;
    }
}

// ================= tf32 mma.sync GEMMs =================
// CTA tile 128x128x32, 8 warps (2 in M x 4 in N), warp tile 64x32, mma m16n8k8.
// A smem: [m][k] 128x32 f32, row = 128B, chunk swizzle c^=(r&7).
// B smem: [k][n] 32x128 f32, row = 512B, chunk swizzle c^=2*(k&3).
// Fragment LDS proven conflict-free for both.

#define STAGE_A_FLOATS 4096
#define STAGE_B_FLOATS 4096

// ---------------- kernel 2: fused gate+up + SiLU ----------------
__global__ void __launch_bounds__(256, 1)
gateup_mma_kernel(const float* __restrict__ X,
                  const float* __restrict__ Wg,
                  const float* __restrict__ Wu) {
    extern __shared__ float smem[];
    float* As  = smem;                  // 3 * 4096
    float* Bgs = smem + 3 * STAGE_A_FLOATS;
    float* Bus = smem + 6 * STAGE_A_FLOATS;

    const int e = blockIdx.z;
    const int cnt = g_count[e];
    const int m0 = blockIdx.x * 128;
    if (m0 >= cnt) return;
    const int n0 = blockIdx.y * 128;

    const int tid = threadIdx.x, wid = tid >> 5, lane = tid & 31;
    const int wm = wid & 1, wn = wid >> 1;
    const int lr = lane >> 2, lc = lane & 3;

    // A gmem->smem mapping: thread -> row (tid>>1), 4 float4 chunks
    const int ar = tid >> 1;
    const bool av = (m0 + ar) < cnt;
    const float* arow = X + (size_t)(av ? g_tok[e * CAP + m0 + ar] : 0) * DDIM;
    const int an = av ? 16 : 0;
    uint32_t aoff[4]; int ac[4];
#pragma unroll
    for (int i = 0; i < 4; i++) {
        int c = (tid & 1) * 4 + i;
        ac[i] = c;
        aoff[i] = (uint32_t)(ar * 128 + ((c ^ (ar & 7)) << 4));
    }
    // B gmem->smem mapping: thread -> k-row (tid>>3), 4 float4 chunks
    const int bk = tid >> 3;
    const float* grow = Wg + ((size_t)e * DDIM + bk) * FDIM + n0;
    const float* urow = Wu + ((size_t)e * DDIM + bk) * FDIM + n0;
    uint32_t boff[4]; int bc[4];
#pragma unroll
    for (int i = 0; i < 4; i++) {
        int c = (tid & 7) + 8 * i;
        bc[i] = c;
        boff[i] = (uint32_t)(bk * 512 + ((c ^ ((bk & 3) << 1)) << 4));
    }

    const uint32_t sA = smem_u32(As), sG = smem_u32(Bgs), sU = smem_u32(Bus);

    float accg[4][4][4], accu[4][4][4];
#pragma unroll
    for (int mi = 0; mi < 4; mi++)
#pragma unroll
        for (int ni = 0; ni < 4; ni++)
#pragma unroll
            for (int q = 0; q < 4; q++) { accg[mi][ni][q] = 0.f; accu[mi][ni][q] = 0.f; }

    const int KT = DDIM / 32;   // 32

#define GU_PREFETCH(s) do { \
    int _buf = (s) % 3; \
    uint32_t _da = sA + _buf * 16384, _dg = sG + _buf * 16384, _du = sU + _buf * 16384; \
    const float* _ap = arow + (s) * 32; \
    const float* _gp = grow + (size_t)(s) * 32 * FDIM; \
    const float* _up = urow + (size_t)(s) * 32 * FDIM; \
    _Pragma("unroll") \
    for (int _i = 0; _i < 4; _i++) { \
        CPA(_da + aoff[_i], _ap + ac[_i] * 4, an); \
        CPA(_dg + boff[_i], _gp + bc[_i] * 4, 16); \
        CPA(_du + boff[_i], _up + bc[_i] * 4, 16); \
    } } while (0)

    GU_PREFETCH(0); CPA_COMMIT();
    GU_PREFETCH(1); CPA_COMMIT();

    for (int s = 0; s < KT; s++) {
        if (s + 2 < KT) { GU_PREFETCH(s + 2); }
        CPA_COMMIT();
        CPA_WAIT2();
        __syncthreads();
        const int buf = s % 3;
        const float* A = As  + buf * STAGE_A_FLOATS;
        const float* G = Bgs + buf * STAGE_B_FLOATS;
        const float* U = Bus + buf * STAGE_B_FLOATS;
#pragma unroll
        for (int k8 = 0; k8 < 4; k8++) {
            uint32_t a[4][4];
#pragma unroll
            for (int mi = 0; mi < 4; mi++) {
                const int r0 = wm * 64 + mi * 16 + lr;
#pragma unroll
                for (int h = 0; h < 2; h++) {
                    const int cx = (((2 * k8 + h) ^ lr) << 2) + lc;
                    a[mi][h * 2 + 0] = cvt_tf32(A[r0 * 32 + cx]);
                    a[mi][h * 2 + 1] = cvt_tf32(A[(r0 + 8) * 32 + cx]);
                }
            }
#pragma unroll
            for (int ni = 0; ni < 4; ni++) {
                const int c = wn * 8 + ni * 2 + (lr >> 2);
                const int bx = ((c ^ (lc << 1)) << 2) + (lr & 3);
                uint32_t bg[2], bu[2];
#pragma unroll
                for (int h = 0; h < 2; h++) {
                    const int off = (k8 * 8 + lc + 4 * h) * 128 + bx;
                    bg[h] = cvt_tf32(G[off]);
                    bu[h] = cvt_tf32(U[off]);
                }
#pragma unroll
                for (int mi = 0; mi < 4; mi++) {
                    MMA_TF32(accg[mi][ni], a[mi], bg);
                    MMA_TF32(accu[mi][ni], a[mi], bu);
                }
            }
        }
        __syncthreads();
    }

    // epilogue: silu(g)*u, direct float2 stores
#pragma unroll
    for (int mi = 0; mi < 4; mi++) {
        const int r = wm * 64 + mi * 16 + lr;
        const size_t row0 = (size_t)e * CAP + m0 + r;
#pragma unroll
        for (int ni = 0; ni < 4; ni++) {
            const int col = n0 + wn * 32 + ni * 8 + 2 * lc;
            if (m0 + r < cnt) {
                float g0 = accg[mi][ni][0], g1 = accg[mi][ni][1];
                float2 v;
                v.x = (g0 / (1.f + __expf(-g0))) * accu[mi][ni][0];
                v.y = (g1 / (1.f + __expf(-g1))) * accu[mi][ni][1];
                *(float2*)&g_act[row0 * FDIM + col] = v;
            }
            if (m0 + r + 8 < cnt) {
                float g2 = accg[mi][ni][2], g3 = accg[mi][ni][3];
                float2 v;
                v.x = (g2 / (1.f + __expf(-g2))) * accu[mi][ni][2];
                v.y = (g3 / (1.f + __expf(-g3))) * accu[mi][ni][3];
                *(float2*)&g_act[(row0 + 8) * FDIM + col] = v;
            }
        }
    }
}

// ---------------- kernel 3: down GEMM ----------------
__global__ void __launch_bounds__(256, 1)
down_mma_kernel(const float* __restrict__ Wd) {
    extern __shared__ float smem[];
    float* As = smem;                   // 3 * 4096
    float* Bs = smem + 3 * STAGE_A_FLOATS;

    const int e = blockIdx.z;
    const int cnt = g_count[e];
    const int m0 = blockIdx.x * 128;
    if (m0 >= cnt) return;
    const int n0 = blockIdx.y * 128;

    const int tid = threadIdx.x, wid = tid >> 5, lane = tid & 31;
    const int wm = wid & 1, wn = wid >> 1;
    const int lr = lane >> 2, lc = lane & 3;

    const int ar = tid >> 1;
    const bool av = (m0 + ar) < cnt;
    const float* arow = g_act + ((size_t)e * CAP + m0 + (av ? ar : 0)) * FDIM;
    const int an = av ? 16 : 0;
    uint32_t aoff[4]; int ac[4];
#pragma unroll
    for (int i = 0; i < 4; i++) {
        int c = (tid & 1) * 4 + i;
        ac[i] = c;
        aoff[i] = (uint32_t)(ar * 128 + ((c ^ (ar & 7)) << 4));
    }
    const int bk = tid >> 3;
    const float* brow = Wd + ((size_t)e * FDIM + bk) * DDIM + n0;
    uint32_t boff[4]; int bc[4];
#pragma unroll
    for (int i = 0; i < 4; i++) {
        int c = (tid & 7) + 8 * i;
        bc[i] = c;
        boff[i] = (uint32_t)(bk * 512 + ((c ^ ((bk & 3) << 1)) << 4));
    }

    const uint32_t sA = smem_u32(As), sB = smem_u32(Bs);

    float acc[4][4][4];
#pragma unroll
    for (int mi = 0; mi < 4; mi++)
#pragma unroll
        for (int ni = 0; ni < 4; ni++)
#pragma unroll
            for (int q = 0; q < 4; q++) acc[mi][ni][q] = 0.f;

    const int KT = FDIM / 32;   // 88

#define DN_PREFETCH(s) do { \
    int _buf = (s) % 3; \
    uint32_t _da = sA + _buf * 16384, _db = sB + _buf * 16384; \
    const float* _ap = arow + (s) * 32; \
    const float* _bp = brow + (size_t)(s) * 32 * DDIM; \
    _Pragma("unroll") \
    for (int _i = 0; _i < 4; _i++) { \
        CPA(_da + aoff[_i], _ap + ac[_i] * 4, an); \
        CPA(_db + boff[_i], _bp + bc[_i] * 4, 16); \
    } } while (0)

    DN_PREFETCH(0); CPA_COMMIT();
    DN_PREFETCH(1); CPA_COMMIT();

    for (int s = 0; s < KT; s++) {
        if (s + 2 < KT) { DN_PREFETCH(s + 2); }
        CPA_COMMIT();
        CPA_WAIT2();
        __syncthreads();
        const int buf = s % 3;
        const float* A = As + buf * STAGE_A_FLOATS;
        const float* B = Bs + buf * STAGE_B_FLOATS;
#pragma unroll
        for (int k8 = 0; k8 < 4; k8++) {
            uint32_t a[4][4];
#pragma unroll
            for (int mi = 0; mi < 4; mi++) {
                const int r0 = wm * 64 + mi * 16 + lr;
#pragma unroll
                for (int h = 0; h < 2; h++) {
                    const int cx = (((2 * k8 + h) ^ lr) << 2) + lc;
                    a[mi][h * 2 + 0] = cvt_tf32(A[r0 * 32 + cx]);
                    a[mi][h * 2 + 1] = cvt_tf32(A[(r0 + 8) * 32 + cx]);
                }
            }
#pragma unroll
            for (int ni = 0; ni < 4; ni++) {
                const int c = wn * 8 + ni * 2 + (lr >> 2);
                const int bx = ((c ^ (lc << 1)) << 2) + (lr & 3);
                uint32_t b[2];
#pragma unroll
                for (int h = 0; h < 2; h++)
                    b[h] = cvt_tf32(B[(k8 * 8 + lc + 4 * h) * 128 + bx]);
#pragma unroll
                for (int mi = 0; mi < 4; mi++)
                    MMA_TF32(acc[mi][ni], a[mi], b);
            }
        }
        __syncthreads();
    }

#pragma unroll
    for (int mi = 0; mi < 4; mi++) {
        const int r = wm * 64 + mi * 16 + lr;
        const size_t row0 = (size_t)e * CAP + m0 + r;
#pragma unroll
        for (int ni = 0; ni < 4; ni++) {
            const int col = n0 + wn * 32 + ni * 8 + 2 * lc;
            if (m0 + r < cnt) {
                float2 v; v.x = acc[mi][ni][0]; v.y = acc[mi][ni][1];
                *(float2*)&g_y[row0 * DDIM + col] = v;
            }
            if (m0 + r + 8 < cnt) {
                float2 v; v.x = acc[mi][ni][2]; v.y = acc[mi][ni][3];
                *(float2*)&g_y[(row0 + 8) * DDIM + col] = v;
            }
        }
    }
}

// ---------------- kernel 4: weighted combine ----------------
__global__ void combine_kernel(float* __restrict__ out) {
    const int g = blockIdx.x * blockDim.x + threadIdx.x;
    const int t = g >> 8;
    const int c = g & 255;
    const int s0 = g_slot[2 * t], s1 = g_slot[2 * t + 1];
    const float w0 = g_wt[2 * t], w1 = g_wt[2 * t + 1];
    const float4* Y = (const float4*)g_y;
    float4 a = Y[(size_t)s0 * 256 + c];
    float4 b = Y[(size_t)s1 * 256 + c];
    float4 o;
    o.x = w0 * a.x + w1 * b.x;
    o.y = w0 * a.y + w1 * b.y;
    o.z = w0 * a.z + w1 * b.z;
    o.w = w0 * a.w + w1 * b.w;
    ((float4*)out)[g] = o;
}

// ---------------- launch ----------------
extern "C" void kernel_launch(void* const* d_in, const int* in_sizes, int n_in,
                              void* d_out, int out_size) {
    const float* x  = (const float*)d_in[0];
    const float* rw = (const float*)d_in[1];
    const float* wg = (const float*)d_in[2];
    const float* wu = (const float*)d_in[3];
    const float* wd = (const float*)d_in[4];
    float* out = (float*)d_out;

    cudaFuncSetAttribute(gateup_mma_kernel, cudaFuncAttributeMaxDynamicSharedMemorySize, 147456);
    cudaFuncSetAttribute(down_mma_kernel,   cudaFuncAttributeMaxDynamicSharedMemorySize, 98304);

    reset_kernel<<<1, 32>>>();
    router_kernel<<<NTOK / 4, 128>>>(x, rw);

    gateup_mma_kernel<<<dim3(CAP / 128, FDIM / 128, NEXP), 256, 147456>>>(x, wg, wu);
    down_mma_kernel<<<dim3(CAP / 128, DDIM / 128, NEXP), 256, 98304>>>(wd);

    combine_kernel<<<(NTOK * 256) / 256, 256>>>(out);
}